// round 15
// baseline (speedup 1.0000x reference)
#include <cuda_runtime.h>
#include <cstdint>
#include <cuda_bf16.h>
#include <mma.h>
#include <math.h>

using namespace nvcuda;

#define B_  8
#define N_  1024
#define D_  1024
#define H_  8
#define DQK 128
#define DV  128
#define UV  4096
#define TB_ 128
#define LOG2C 0.69314718056f

typedef __nv_bfloat16 bf16;

// ---------------- scratch (zero-initialized device globals) ----------------
__device__ float g_x[B_*N_*D_];
__device__ float g_h[B_*N_*D_];
__device__ float g_rab[(size_t)B_*N_*N_];
__device__ float g_o[B_*N_*D_];
__device__ float g_pool[B_*D_];
__device__ float g_ppart[8*B_*D_];
__device__ int   g_len[B_];
__device__ bf16  g_ah[B_*N_*D_];
__device__ bf16  g_al[B_*N_*D_];
__device__ bf16  g_wh[D_*UV];
__device__ bf16  g_wl[D_*UV];
__device__ bf16  g_uvh[(size_t)B_*N_*UV];
__device__ bf16  g_uvl[(size_t)B_*N_*UV];

// ---------------- helpers ----------------
__device__ __forceinline__ float block_sum256(float v, float* red) {
#pragma unroll
    for (int o = 16; o > 0; o >>= 1) v += __shfl_xor_sync(0xffffffffu, v, o);
    int warp = threadIdx.x >> 5, lane = threadIdx.x & 31;
    if (lane == 0) red[warp] = v;
    __syncthreads();
    if (warp == 0) {
        float t = (lane < 8) ? red[lane] : 0.f;
#pragma unroll
        for (int o = 4; o > 0; o >>= 1) t += __shfl_xor_sync(0xffffffffu, t, o);
        if (lane == 0) red[0] = t;
    }
    __syncthreads();
    float r = red[0];
    __syncthreads();
    return r;
}

__device__ __forceinline__ float silu_f(float v) { return v / (1.f + expf(-v)); }

__device__ __forceinline__ void split_bf(float v, bf16& h, bf16& l) {
    h = __float2bfloat16(v);
    l = __float2bfloat16(v - __bfloat162float(h));
}

__device__ __forceinline__ void cp16(void* dst, const void* src) {
    unsigned int s = (unsigned int)__cvta_generic_to_shared(dst);
    asm volatile("cp.async.cg.shared.global [%0], [%1], 16;\n" :: "r"(s), "l"(src));
}
__device__ __forceinline__ void cp_commit() { asm volatile("cp.async.commit_group;\n"); }
template <int NN>
__device__ __forceinline__ void cp_wait() { asm volatile("cp.async.wait_group %0;\n" :: "n"(NN)); }

// ---------------- elementwise ----------------
__global__ void prep_kernel(const float* __restrict__ x, const float* __restrict__ mask) {
    int idx = blockIdx.x * 256 + threadIdx.x;
    g_x[idx] = x[idx] * mask[idx >> 10];
}

__global__ void len_kernel(const float* __restrict__ mask) {
    __shared__ float red[32];
    int b = blockIdx.x;
    float s = 0.f;
    for (int i = threadIdx.x; i < N_; i += 256) s += mask[b * N_ + i];
    float t = block_sum256(s, red);
    if (threadIdx.x == 0) g_len[b] = (int)(t + 0.5f);
}

__global__ void rab_kernel(const int* __restrict__ ts,
                           const float* __restrict__ pos_w,
                           const float* __restrict__ ts_w) {
    int idx = blockIdx.x * 256 + threadIdx.x;
    int b = idx >> 20;
    int rem = idx & ((1 << 20) - 1);
    int n = rem >> 10;
    if (n >= g_len[b]) return;                 // dead q-row: rab never read live
    int m = rem & 1023;
    int tn = ts[b * N_ + ((n + 1 < N_) ? n + 1 : N_ - 1)];
    int dlt = tn - ts[b * N_ + m];
    float ad = fmaxf(fabsf((float)dlt), 1.0f);
    int bucket = (int)(logf(ad) / LOG2C);
    bucket = bucket < 0 ? 0 : (bucket > TB_ ? TB_ : bucket);
    g_rab[idx] = pos_w[n - m + N_ - 1] + ts_w[bucket];
}

__global__ void split_w_kernel(const float* __restrict__ w, bf16* __restrict__ wh,
                               bf16* __restrict__ wl, int n4) {
    int i = blockIdx.x * 256 + threadIdx.x;
    if (i >= n4) return;
    float4 v = ((const float4*)w)[i];
    bf16 h[4], l[4];
    split_bf(v.x, h[0], l[0]); split_bf(v.y, h[1], l[1]);
    split_bf(v.z, h[2], l[2]); split_bf(v.w, h[3], l[3]);
    ((uint2*)wh)[i] = *(uint2*)h;
    ((uint2*)wl)[i] = *(uint2*)l;
}

// ---------------- layer norm -> bf16 hi/lo (skips dead rows) ----------------
// gate (optional): u reconstructed from bf16 hi+lo pair (error ~2^-17, negligible)
__global__ void ln_kernel(const float* __restrict__ in,
                          const float* __restrict__ gamma,
                          const float* __restrict__ beta,
                          bf16* __restrict__ outh, bf16* __restrict__ outl,
                          const bf16* __restrict__ uh, const bf16* __restrict__ ul) {
    int row = blockIdx.x;
    if ((row & (N_ - 1)) >= g_len[row >> 10]) return;   // dead row (never observed)
    __shared__ float red[32];
    const float* x = in + (size_t)row * D_;
    int tid = threadIdx.x;
    float v[4]; float s = 0.f;
#pragma unroll
    for (int i = 0; i < 4; i++) { v[i] = x[tid + i * 256]; s += v[i]; }
    float mu = block_sum256(s, red) * (1.0f / D_);
    float s2 = 0.f;
#pragma unroll
    for (int i = 0; i < 4; i++) { float d = v[i] - mu; s2 += d * d; }
    float var = block_sum256(s2, red) * (1.0f / D_);
    float inv = rsqrtf(var + 1e-6f);
#pragma unroll
    for (int i = 0; i < 4; i++) {
        int d = tid + i * 256;
        float y = (v[i] - mu) * inv * gamma[d] + beta[d];
        if (uh) {
            size_t gi = (size_t)row * UV + d;
            y *= __bfloat162float(uh[gi]) + __bfloat162float(ul[gi]);
        }
        bf16 h, l; split_bf(y, h, l);
        outh[(size_t)row * D_ + d] = h;
        outl[(size_t)row * D_ + d] = l;
    }
}

// ---------------- 3xBF16 GEMM, double-buffered cp.async, fused epilogue ----------------
#define BM 128
#define BN 128
#define BK 32
#define LDA_ 40
#define LDB_ 136
#define ABF (BM*LDA_)
#define BBF (BK*LDB_)
#define SBUF (2*ABF + 2*BBF)
#define GSMEM (2*SBUF*2)   // 75776 bytes -> 2 CTAs/SM
#define LDS_ 136

template <int EPI>
__global__ __launch_bounds__(256, 2) void gemm_bf16(const bf16* __restrict__ Ah,
                                                    const bf16* __restrict__ Al,
                                                    const bf16* __restrict__ Bh,
                                                    const bf16* __restrict__ Bl,
                                                    float* __restrict__ C,
                                                    const float* __restrict__ bias,
                                                    bf16* __restrict__ Ch,
                                                    bf16* __restrict__ Cl,
                                                    int M, int Nd, int K) {
    int row0 = blockIdx.y * BM;
    if ((row0 & (N_ - 1)) >= g_len[row0 >> 10]) return;

    extern __shared__ char smraw[];
    bf16* sm = (bf16*)smraw;
    float* stage = (float*)smraw;

    int tid = threadIdx.x;
    int warp = tid >> 5;
    int wm = warp >> 1, wn = warp & 1;
    int col0 = blockIdx.x * BN;

    wmma::fragment<wmma::accumulator, 16, 16, 16, float> acc[2][4];
#pragma unroll
    for (int i = 0; i < 2; i++)
#pragma unroll
        for (int j = 0; j < 4; j++) wmma::fill_fragment(acc[i][j], 0.f);

    auto load_tiles = [&](int buf, int k0) {
        bf16* sAh = sm + buf * SBUF;
        bf16* sAl = sAh + ABF;
        bf16* sBh = sAh + 2 * ABF;
        bf16* sBl = sBh + BBF;
#pragma unroll
        for (int i = 0; i < 2; i++) {
            int lin = tid + i * 256;
            int r = lin >> 2, c8 = lin & 3;
            cp16(&sAh[r * LDA_ + c8 * 8], Ah + (size_t)(row0 + r) * K + k0 + c8 * 8);
            cp16(&sAl[r * LDA_ + c8 * 8], Al + (size_t)(row0 + r) * K + k0 + c8 * 8);
        }
#pragma unroll
        for (int i = 0; i < 2; i++) {
            int lin = tid + i * 256;
            int r = lin >> 4, c8 = lin & 15;
            cp16(&sBh[r * LDB_ + c8 * 8], Bh + (size_t)(k0 + r) * Nd + col0 + c8 * 8);
            cp16(&sBl[r * LDB_ + c8 * 8], Bl + (size_t)(k0 + r) * Nd + col0 + c8 * 8);
        }
        cp_commit();
    };

    load_tiles(0, 0);

    int nk = K / BK;
    for (int it = 0; it < nk; it++) {
        int cur = it & 1;
        if (it + 1 < nk) { load_tiles(cur ^ 1, (it + 1) * BK); cp_wait<1>(); }
        else             { cp_wait<0>(); }
        __syncthreads();

        const bf16* sAh = sm + cur * SBUF;
        const bf16* sAl = sAh + ABF;
        const bf16* sBh = sAh + 2 * ABF;
        const bf16* sBl = sBh + BBF;
#pragma unroll
        for (int kk = 0; kk < BK; kk += 16) {
            wmma::fragment<wmma::matrix_a, 16, 16, 16, bf16, wmma::row_major> ah[2], al[2];
#pragma unroll
            for (int i = 0; i < 2; i++) {
                wmma::load_matrix_sync(ah[i], sAh + (wm * 32 + i * 16) * LDA_ + kk, LDA_);
                wmma::load_matrix_sync(al[i], sAl + (wm * 32 + i * 16) * LDA_ + kk, LDA_);
            }
#pragma unroll
            for (int j = 0; j < 4; j++) {
                wmma::fragment<wmma::matrix_b, 16, 16, 16, bf16, wmma::row_major> bh, bl;
                wmma::load_matrix_sync(bh, sBh + kk * LDB_ + wn * 64 + j * 16, LDB_);
                wmma::load_matrix_sync(bl, sBl + kk * LDB_ + wn * 64 + j * 16, LDB_);
                wmma::mma_sync(acc[0][j], ah[0], bl, acc[0][j]);
                wmma::mma_sync(acc[1][j], ah[1], bl, acc[1][j]);
                wmma::mma_sync(acc[0][j], al[0], bh, acc[0][j]);
                wmma::mma_sync(acc[1][j], al[1], bh, acc[1][j]);
                wmma::mma_sync(acc[0][j], ah[0], bh, acc[0][j]);
                wmma::mma_sync(acc[1][j], ah[1], bh, acc[1][j]);
            }
        }
        __syncthreads();
    }

#pragma unroll
    for (int i = 0; i < 2; i++)
#pragma unroll
        for (int j = 0; j < 4; j++)
            wmma::store_matrix_sync(&stage[(wm * 32 + i * 16) * LDS_ + wn * 64 + j * 16],
                                    acc[i][j], LDS_, wmma::mem_row_major);
    __syncthreads();
#pragma unroll
    for (int i = 0; i < 16; i++) {
        int lin = tid + i * 256;
        int r = lin >> 5, c4 = lin & 31;
        int col = c4 * 4;
        float4 v = *(float4*)(&stage[r * LDS_ + col]);
        size_t gi = (size_t)(row0 + r) * Nd + col0 + col;
        if (EPI == 1) {
            v.x = silu_f(v.x + bias[col0 + col + 0]);
            v.y = silu_f(v.y + bias[col0 + col + 1]);
            v.z = silu_f(v.z + bias[col0 + col + 2]);
            v.w = silu_f(v.w + bias[col0 + col + 3]);
            bf16 h[4], l[4];
            split_bf(v.x, h[0], l[0]); split_bf(v.y, h[1], l[1]);
            split_bf(v.z, h[2], l[2]); split_bf(v.w, h[3], l[3]);
            *(uint2*)(&Ch[gi]) = *(uint2*)h;
            *(uint2*)(&Cl[gi]) = *(uint2*)l;
        } else {
            float4 xo = *(const float4*)(&C[gi]);
            v.x = xo.x + v.x + bias[col0 + col + 0];
            v.y = xo.y + v.y + bias[col0 + col + 1];
            v.z = xo.z + v.z + bias[col0 + col + 2];
            v.w = xo.w + v.w + bias[col0 + col + 3];
            *(float4*)(&C[gi]) = v;
        }
    }
}

// ---------------- fused causal SiLU attention, 64x64 tiles, 512 thr, KV pipelined ----------------
// full 3xBF16 on BOTH MMAs (round-14 showed dropping ANY lo term costs ~1e-3 rel_err)
#define QLD 136            // bf16 elems per row (128 + pad)
#define QTB 17408          // one 64x136 bf16 tile in bytes
#define SLD 68             // fp32 S
#define SBLD 72            // bf16 S hi/lo
#define OFF_QH 0
#define OFF_QL QTB
#define OFF_KV (2*QTB)     // 2 buffers x (KH,KL,VH,VL) each QTB
#define KVB    (4*QTB)     // one buffer set = 69632 B
#define OFF_S  (OFF_KV + 2*KVB)            // 174080
#define OFF_SH (OFF_S + 64*SLD*4)          // 191488
#define OFF_SL (OFF_SH + 64*SBLD*2)        // 200704
#define ASMEM  (OFF_SL + 64*SBLD*2)        // 209920 bytes

__global__ __launch_bounds__(512) void attn_kernel(const float* __restrict__ mask) {
    int qt = (gridDim.x - 1) - blockIdx.x;     // long tiles first
    int h = blockIdx.y, b = blockIdx.z;
    int q0 = qt * 64;
    int len = g_len[b];
    if (q0 >= len) return;
    int mtmax = qt;
    {
        int ml = (len - 1) >> 6;
        if (ml < mtmax) mtmax = ml;
    }

    extern __shared__ char smraw[];
    bf16* sQh = (bf16*)(smraw + OFF_QH);
    bf16* sQl = (bf16*)(smraw + OFF_QL);
    float* sS = (float*)(smraw + OFF_S);
    bf16* sSh = (bf16*)(smraw + OFF_SH);
    bf16* sSl = (bf16*)(smraw + OFF_SL);

    int tid = threadIdx.x;
    int warp = tid >> 5;
    int wr = warp >> 2, wc = warp & 3;          // 4x4 warp grid

    const size_t rs = UV;
    const size_t qoff = ((size_t)(b * N_) + q0) * rs + 2 * H_ * DV + h * DQK;
#pragma unroll
    for (int i = 0; i < 2; i++) {
        int lin = tid + i * 512;
        int r = lin >> 4, c8 = lin & 15;
        *(uint4*)(&sQh[r * QLD + c8 * 8]) = *(const uint4*)(g_uvh + qoff + (size_t)r * rs + c8 * 8);
        *(uint4*)(&sQl[r * QLD + c8 * 8]) = *(const uint4*)(g_uvl + qoff + (size_t)r * rs + c8 * 8);
    }

    auto load_kv = [&](int buf, int m0) {
        bf16* sKh = (bf16*)(smraw + OFF_KV + buf * KVB);
        bf16* sKl = sKh + QTB / 2;
        bf16* sVh = sKh + QTB;
        bf16* sVl = sKh + 3 * QTB / 2;
        const size_t koff = ((size_t)(b * N_) + m0) * rs + 2 * H_ * DV + H_ * DQK + h * DQK;
        const size_t voff = ((size_t)(b * N_) + m0) * rs + H_ * DV + h * DV;
#pragma unroll
        for (int i = 0; i < 2; i++) {
            int lin = tid + i * 512;
            int r = lin >> 4, c8 = lin & 15;
            cp16(&sKh[r * QLD + c8 * 8], g_uvh + koff + (size_t)r * rs + c8 * 8);
            cp16(&sKl[r * QLD + c8 * 8], g_uvl + koff + (size_t)r * rs + c8 * 8);
            cp16(&sVh[r * QLD + c8 * 8], g_uvh + voff + (size_t)r * rs + c8 * 8);
            cp16(&sVl[r * QLD + c8 * 8], g_uvl + voff + (size_t)r * rs + c8 * 8);
        }
        cp_commit();
    };

    wmma::fragment<wmma::accumulator, 16, 16, 16, float> accO[2];
#pragma unroll
    for (int j = 0; j < 2; j++) wmma::fill_fragment(accO[j], 0.f);

    load_kv(0, 0);

    for (int mt = 0; mt <= mtmax; mt++) {
        int buf = mt & 1;
        int m0 = mt * 64;
        if (mt < mtmax) { load_kv(buf ^ 1, (mt + 1) * 64); cp_wait<1>(); }
        else            { cp_wait<0>(); }
        __syncthreads();

        bf16* sKh = (bf16*)(smraw + OFF_KV + buf * KVB);
        bf16* sKl = sKh + QTB / 2;
        bf16* sVh = sKh + QTB;
        bf16* sVl = sKh + 3 * QTB / 2;

        // S = Q @ K^T : one 16x16 tile per warp (3xBF16)
        wmma::fragment<wmma::accumulator, 16, 16, 16, float> accS;
        wmma::fill_fragment(accS, 0.f);
#pragma unroll
        for (int kk = 0; kk < DQK; kk += 16) {
            wmma::fragment<wmma::matrix_a, 16, 16, 16, bf16, wmma::row_major> ah, al;
            wmma::load_matrix_sync(ah, sQh + (wr * 16) * QLD + kk, QLD);
            wmma::load_matrix_sync(al, sQl + (wr * 16) * QLD + kk, QLD);
            wmma::fragment<wmma::matrix_b, 16, 16, 16, bf16, wmma::col_major> bh, bl;
            wmma::load_matrix_sync(bh, sKh + (wc * 16) * QLD + kk, QLD);
            wmma::load_matrix_sync(bl, sKl + (wc * 16) * QLD + kk, QLD);
            wmma::mma_sync(accS, ah, bl, accS);
            wmma::mma_sync(accS, al, bh, accS);
            wmma::mma_sync(accS, ah, bh, accS);
        }
        wmma::store_matrix_sync(&sS[(wr * 16) * SLD + wc * 16], accS,
                                SLD, wmma::mem_row_major);
        __syncthreads();

        // epilogue -> bf16 hi/lo S
#pragma unroll
        for (int i = 0; i < 8; i++) {
            int lin = tid + i * 512;
            int r = lin >> 6, c = lin & 63;
            int qrow = q0 + r, mcol = m0 + c;
            float v = sS[r * SLD + c] + g_rab[((size_t)b * N_ + qrow) * N_ + mcol];
            v = silu_f(v) * (1.0f / N_);
            if (mcol > qrow) v = 0.f;
            v *= mask[b * N_ + mcol];
            bf16 hh, ll; split_bf(v, hh, ll);
            sSh[r * SBLD + c] = hh;
            sSl[r * SBLD + c] = ll;
        }
        __syncthreads();

        // O += S @ V : warp computes 16x32 (3xBF16)
#pragma unroll
        for (int kk = 0; kk < 64; kk += 16) {
            wmma::fragment<wmma::matrix_a, 16, 16, 16, bf16, wmma::row_major> ah, al;
            wmma::load_matrix_sync(ah, sSh + (wr * 16) * SBLD + kk, SBLD);
            wmma::load_matrix_sync(al, sSl + (wr * 16) * SBLD + kk, SBLD);
#pragma unroll
            for (int j = 0; j < 2; j++) {
                wmma::fragment<wmma::matrix_b, 16, 16, 16, bf16, wmma::row_major> bh, bl;
                wmma::load_matrix_sync(bh, sVh + kk * QLD + wc * 32 + j * 16, QLD);
                wmma::load_matrix_sync(bl, sVl + kk * QLD + wc * 32 + j * 16, QLD);
                wmma::mma_sync(accO[j], ah, bl, accO[j]);
                wmma::mma_sync(accO[j], al, bh, accO[j]);
                wmma::mma_sync(accO[j], ah, bh, accO[j]);
            }
        }
        __syncthreads();
    }
#pragma unroll
    for (int j = 0; j < 2; j++)
        wmma::store_matrix_sync(&g_o[((size_t)(b * N_) + q0 + wr * 16) * D_ + h * DV + wc * 32 + j * 16],
                                accO[j], D_, wmma::mem_row_major);
}

// ---------------- pooling ----------------
__global__ void norm_rows_kernel(const float* __restrict__ in, float* __restrict__ out,
                                 int use_len) {
    int row = blockIdx.x;
    if (use_len && (row & (N_ - 1)) >= g_len[row >> 10]) return;   // dead row
    __shared__ float red[32];
    const float* x = in + (size_t)row * D_;
    int tid = threadIdx.x;
    float v[4]; float s2 = 0.f;
#pragma unroll
    for (int i = 0; i < 4; i++) { v[i] = x[tid + i * 256]; s2 += v[i] * v[i]; }
    float nrm = sqrtf(block_sum256(s2, red));
    float inv = 1.0f / fmaxf(nrm, 1e-12f);
#pragma unroll
    for (int i = 0; i < 4; i++) out[(size_t)row * D_ + tid + i * 256] = v[i] * inv;
}

__global__ void pool_part_kernel(const float* __restrict__ ue, const float* __restrict__ mask) {
    int b = blockIdx.y;
    int seg = blockIdx.z;
    int d = blockIdx.x * 256 + threadIdx.x;
    float acc = 0.f;
    int n0 = seg * 128;
#pragma unroll 4
    for (int n = n0; n < n0 + 128; n++)
        acc += ue[((size_t)b * N_ + n) * D_ + d] * mask[b * N_ + n];
    g_ppart[((size_t)seg * B_ + b) * D_ + d] = acc;
}

__global__ void pool_final_kernel(const float* __restrict__ ue) {
    int b = blockIdx.y;
    int d = blockIdx.x * 256 + threadIdx.x;
    float acc = 0.f;
#pragma unroll
    for (int seg = 0; seg < 8; seg++) acc += g_ppart[((size_t)seg * B_ + b) * D_ + d];
    int len = g_len[b];
    float last = ue[((size_t)b * N_ + (len - 1)) * D_ + d];
    g_pool[b * D_ + d] = 0.5f * (last + acc / (float)len);
}

// ---------------- host ----------------
extern "C" void kernel_launch(void* const* d_in, const int* in_sizes, int n_in,
                              void* d_out, int out_size) {
    const float* x      = (const float*)d_in[0];
    const int*   ts     = (const int*)d_in[1];
    const float* mask   = (const float*)d_in[2];
    const float* ln1_g  = (const float*)d_in[3];
    const float* ln1_b  = (const float*)d_in[4];
    const float* w_uvqk = (const float*)d_in[5];
    const float* b_uvqk = (const float*)d_in[6];
    const float* ln2_g  = (const float*)d_in[7];
    const float* ln2_b  = (const float*)d_in[8];
    const float* w_o    = (const float*)d_in[9];
    const float* b_o    = (const float*)d_in[10];
    const float* pos_w  = (const float*)d_in[11];
    const float* ts_w   = (const float*)d_in[12];
    float* out = (float*)d_out;

    static bool attr_done = false;
    if (!attr_done) {
        cudaFuncSetAttribute(gemm_bf16<1>, cudaFuncAttributeMaxDynamicSharedMemorySize, GSMEM);
        cudaFuncSetAttribute(gemm_bf16<2>, cudaFuncAttributeMaxDynamicSharedMemorySize, GSMEM);
        cudaFuncSetAttribute(attn_kernel,  cudaFuncAttributeMaxDynamicSharedMemorySize, ASMEM);
        attr_done = true;
    }

    float *px, *ph, *po, *ppool;
    bf16 *pah, *pal, *pwh, *pwl, *puvh, *puvl;
    cudaGetSymbolAddress((void**)&px, g_x);
    cudaGetSymbolAddress((void**)&ph, g_h);
    cudaGetSymbolAddress((void**)&po, g_o);
    cudaGetSymbolAddress((void**)&ppool, g_pool);
    cudaGetSymbolAddress((void**)&pah, g_ah);
    cudaGetSymbolAddress((void**)&pal, g_al);
    cudaGetSymbolAddress((void**)&pwh, g_wh);
    cudaGetSymbolAddress((void**)&pwl, g_wl);
    cudaGetSymbolAddress((void**)&puvh, g_uvh);
    cudaGetSymbolAddress((void**)&puvl, g_uvl);

    prep_kernel<<<(B_*N_*D_)/256, 256>>>(x, mask);
    len_kernel<<<B_, 256>>>(mask);
    rab_kernel<<<(B_*N_*N_)/256, 256>>>(ts, pos_w, ts_w);

    for (int l = 0; l < 2; l++) {
        split_w_kernel<<<(D_*UV/4 + 255)/256, 256>>>(w_uvqk + (size_t)l*D_*UV, pwh, pwl, D_*UV/4);
        ln_kernel<<<B_*N_, 256>>>(px, ln1_g + l*D_, ln1_b + l*D_, pah, pal, nullptr, nullptr);
        gemm_bf16<1><<<dim3(UV/BN, (B_*N_)/BM), 256, GSMEM>>>(
            pah, pal, pwh, pwl, nullptr, b_uvqk + l*UV, puvh, puvl, B_*N_, UV, D_);
        attn_kernel<<<dim3(N_/64, H_, B_), 512, ASMEM>>>(mask);
        ln_kernel<<<B_*N_, 256>>>(po, ln2_g + l*D_, ln2_b + l*D_, pah, pal, puvh, puvl);
        split_w_kernel<<<(D_*D_/4 + 255)/256, 256>>>(w_o + (size_t)l*D_*D_, pwh, pwl, D_*D_/4);
        gemm_bf16<2><<<dim3(D_/BN, (B_*N_)/BM), 256, GSMEM>>>(
            pah, pal, pwh, pwl, px, b_o + l*D_, nullptr, nullptr, B_*N_, D_, D_);
    }

    norm_rows_kernel<<<B_*N_, 256>>>(px, ph, 1);
    pool_part_kernel<<<dim3(D_/256, B_, 8), 256>>>(ph, mask);
    pool_final_kernel<<<dim3(D_/256, B_), 256>>>(ph);
    norm_rows_kernel<<<B_, 256>>>(ppool, out, 0);
}

// round 16
// speedup vs baseline: 1.4944x; 1.4944x over previous
#include <cuda_runtime.h>
#include <cstdint>
#include <cuda_bf16.h>
#include <mma.h>
#include <math.h>

using namespace nvcuda;

#define B_  8
#define N_  1024
#define D_  1024
#define H_  8
#define DQK 128
#define DV  128
#define UV  4096
#define TB_ 128
#define LOG2C 0.69314718056f

typedef __nv_bfloat16 bf16;

// ---------------- scratch (zero-initialized device globals) ----------------
__device__ float g_x[B_*N_*D_];
__device__ float g_h[B_*N_*D_];
__device__ float g_uvqk[(size_t)B_*N_*UV];
__device__ float g_rab[(size_t)B_*N_*N_];
__device__ float g_o[B_*N_*D_];
__device__ float g_pool[B_*D_];
__device__ float g_ppart[8*B_*D_];
__device__ int   g_len[B_];
__device__ bf16  g_ah[B_*N_*D_];
__device__ bf16  g_al[B_*N_*D_];
__device__ bf16  g_wh[D_*UV];
__device__ bf16  g_wl[D_*UV];
__device__ bf16  g_uvh[(size_t)B_*N_*UV];
__device__ bf16  g_uvl[(size_t)B_*N_*UV];

// ---------------- helpers ----------------
__device__ __forceinline__ float block_sum256(float v, float* red) {
#pragma unroll
    for (int o = 16; o > 0; o >>= 1) v += __shfl_xor_sync(0xffffffffu, v, o);
    int warp = threadIdx.x >> 5, lane = threadIdx.x & 31;
    if (lane == 0) red[warp] = v;
    __syncthreads();
    if (warp == 0) {
        float t = (lane < 8) ? red[lane] : 0.f;
#pragma unroll
        for (int o = 4; o > 0; o >>= 1) t += __shfl_xor_sync(0xffffffffu, t, o);
        if (lane == 0) red[0] = t;
    }
    __syncthreads();
    float r = red[0];
    __syncthreads();
    return r;
}

__device__ __forceinline__ float silu_f(float v) { return v / (1.f + expf(-v)); }

__device__ __forceinline__ void split_bf(float v, bf16& h, bf16& l) {
    h = __float2bfloat16(v);
    l = __float2bfloat16(v - __bfloat162float(h));
}

__device__ __forceinline__ void cp16(void* dst, const void* src) {
    unsigned int s = (unsigned int)__cvta_generic_to_shared(dst);
    asm volatile("cp.async.cg.shared.global [%0], [%1], 16;\n" :: "r"(s), "l"(src));
}
__device__ __forceinline__ void cp_commit() { asm volatile("cp.async.commit_group;\n"); }
template <int NN>
__device__ __forceinline__ void cp_wait() { asm volatile("cp.async.wait_group %0;\n" :: "n"(NN)); }

// ---------------- elementwise ----------------
__global__ void prep_kernel(const float* __restrict__ x, const float* __restrict__ mask) {
    int idx = blockIdx.x * 256 + threadIdx.x;
    g_x[idx] = x[idx] * mask[idx >> 10];
}

__global__ void len_kernel(const float* __restrict__ mask) {
    __shared__ float red[32];
    int b = blockIdx.x;
    float s = 0.f;
    for (int i = threadIdx.x; i < N_; i += 256) s += mask[b * N_ + i];
    float t = block_sum256(s, red);
    if (threadIdx.x == 0) g_len[b] = (int)(t + 0.5f);
}

__global__ void rab_kernel(const int* __restrict__ ts,
                           const float* __restrict__ pos_w,
                           const float* __restrict__ ts_w) {
    int idx = blockIdx.x * 256 + threadIdx.x;
    int b = idx >> 20;
    int rem = idx & ((1 << 20) - 1);
    int n = rem >> 10;
    if (n >= g_len[b]) return;                 // dead q-row: rab never read live
    int m = rem & 1023;
    int tn = ts[b * N_ + ((n + 1 < N_) ? n + 1 : N_ - 1)];
    int dlt = tn - ts[b * N_ + m];
    float ad = fmaxf(fabsf((float)dlt), 1.0f);
    int bucket = (int)(logf(ad) / LOG2C);
    bucket = bucket < 0 ? 0 : (bucket > TB_ ? TB_ : bucket);
    g_rab[idx] = pos_w[n - m + N_ - 1] + ts_w[bucket];
}

__global__ void split_w_kernel(const float* __restrict__ w, bf16* __restrict__ wh,
                               bf16* __restrict__ wl, int n4) {
    int i = blockIdx.x * 256 + threadIdx.x;
    if (i >= n4) return;
    float4 v = ((const float4*)w)[i];
    bf16 h[4], l[4];
    split_bf(v.x, h[0], l[0]); split_bf(v.y, h[1], l[1]);
    split_bf(v.z, h[2], l[2]); split_bf(v.w, h[3], l[3]);
    ((uint2*)wh)[i] = *(uint2*)h;
    ((uint2*)wl)[i] = *(uint2*)l;
}

// ---------------- layer norm -> bf16 hi/lo (skips dead rows) ----------------
__global__ void ln_kernel(const float* __restrict__ in,
                          const float* __restrict__ gamma,
                          const float* __restrict__ beta,
                          bf16* __restrict__ outh, bf16* __restrict__ outl,
                          const float* __restrict__ ubase) {
    int row = blockIdx.x;
    if ((row & (N_ - 1)) >= g_len[row >> 10]) return;   // dead row (never observed)
    __shared__ float red[32];
    const float* x = in + (size_t)row * D_;
    int tid = threadIdx.x;
    float v[4]; float s = 0.f;
#pragma unroll
    for (int i = 0; i < 4; i++) { v[i] = x[tid + i * 256]; s += v[i]; }
    float mu = block_sum256(s, red) * (1.0f / D_);
    float s2 = 0.f;
#pragma unroll
    for (int i = 0; i < 4; i++) { float d = v[i] - mu; s2 += d * d; }
    float var = block_sum256(s2, red) * (1.0f / D_);
    float inv = rsqrtf(var + 1e-6f);
#pragma unroll
    for (int i = 0; i < 4; i++) {
        int d = tid + i * 256;
        float y = (v[i] - mu) * inv * gamma[d] + beta[d];
        if (ubase) y *= ubase[(size_t)row * UV + d];
        bf16 h, l; split_bf(y, h, l);
        outh[(size_t)row * D_ + d] = h;
        outl[(size_t)row * D_ + d] = l;
    }
}

// ---------------- 3xBF16 GEMM, double-buffered cp.async, fused epilogue ----------------
#define BM 128
#define BN 128
#define BK 32
#define LDA_ 40
#define LDB_ 136
#define ABF (BM*LDA_)
#define BBF (BK*LDB_)
#define SBUF (2*ABF + 2*BBF)
#define GSMEM (2*SBUF*2)   // 75776 bytes -> 2 CTAs/SM
#define LDS_ 136

template <int EPI>
__global__ __launch_bounds__(256, 2) void gemm_bf16(const bf16* __restrict__ Ah,
                                                    const bf16* __restrict__ Al,
                                                    const bf16* __restrict__ Bh,
                                                    const bf16* __restrict__ Bl,
                                                    float* __restrict__ C,
                                                    const float* __restrict__ bias,
                                                    bf16* __restrict__ Ch,
                                                    bf16* __restrict__ Cl,
                                                    int M, int Nd, int K) {
    int row0 = blockIdx.y * BM;
    if ((row0 & (N_ - 1)) >= g_len[row0 >> 10]) return;

    extern __shared__ char smraw[];
    bf16* sm = (bf16*)smraw;
    float* stage = (float*)smraw;

    int tid = threadIdx.x;
    int warp = tid >> 5;
    int wm = warp >> 1, wn = warp & 1;
    int col0 = blockIdx.x * BN;

    wmma::fragment<wmma::accumulator, 16, 16, 16, float> acc[2][4];
#pragma unroll
    for (int i = 0; i < 2; i++)
#pragma unroll
        for (int j = 0; j < 4; j++) wmma::fill_fragment(acc[i][j], 0.f);

    auto load_tiles = [&](int buf, int k0) {
        bf16* sAh = sm + buf * SBUF;
        bf16* sAl = sAh + ABF;
        bf16* sBh = sAh + 2 * ABF;
        bf16* sBl = sBh + BBF;
#pragma unroll
        for (int i = 0; i < 2; i++) {
            int lin = tid + i * 256;
            int r = lin >> 2, c8 = lin & 3;
            cp16(&sAh[r * LDA_ + c8 * 8], Ah + (size_t)(row0 + r) * K + k0 + c8 * 8);
            cp16(&sAl[r * LDA_ + c8 * 8], Al + (size_t)(row0 + r) * K + k0 + c8 * 8);
        }
#pragma unroll
        for (int i = 0; i < 2; i++) {
            int lin = tid + i * 256;
            int r = lin >> 4, c8 = lin & 15;
            cp16(&sBh[r * LDB_ + c8 * 8], Bh + (size_t)(k0 + r) * Nd + col0 + c8 * 8);
            cp16(&sBl[r * LDB_ + c8 * 8], Bl + (size_t)(k0 + r) * Nd + col0 + c8 * 8);
        }
        cp_commit();
    };

    load_tiles(0, 0);

    int nk = K / BK;
    for (int it = 0; it < nk; it++) {
        int cur = it & 1;
        if (it + 1 < nk) { load_tiles(cur ^ 1, (it + 1) * BK); cp_wait<1>(); }
        else             { cp_wait<0>(); }
        __syncthreads();

        const bf16* sAh = sm + cur * SBUF;
        const bf16* sAl = sAh + ABF;
        const bf16* sBh = sAh + 2 * ABF;
        const bf16* sBl = sBh + BBF;
#pragma unroll
        for (int kk = 0; kk < BK; kk += 16) {
            wmma::fragment<wmma::matrix_a, 16, 16, 16, bf16, wmma::row_major> ah[2], al[2];
#pragma unroll
            for (int i = 0; i < 2; i++) {
                wmma::load_matrix_sync(ah[i], sAh + (wm * 32 + i * 16) * LDA_ + kk, LDA_);
                wmma::load_matrix_sync(al[i], sAl + (wm * 32 + i * 16) * LDA_ + kk, LDA_);
            }
#pragma unroll
            for (int j = 0; j < 4; j++) {
                wmma::fragment<wmma::matrix_b, 16, 16, 16, bf16, wmma::row_major> bh, bl;
                wmma::load_matrix_sync(bh, sBh + kk * LDB_ + wn * 64 + j * 16, LDB_);
                wmma::load_matrix_sync(bl, sBl + kk * LDB_ + wn * 64 + j * 16, LDB_);
                wmma::mma_sync(acc[0][j], ah[0], bl, acc[0][j]);
                wmma::mma_sync(acc[1][j], ah[1], bl, acc[1][j]);
                wmma::mma_sync(acc[0][j], al[0], bh, acc[0][j]);
                wmma::mma_sync(acc[1][j], al[1], bh, acc[1][j]);
                wmma::mma_sync(acc[0][j], ah[0], bh, acc[0][j]);
                wmma::mma_sync(acc[1][j], ah[1], bh, acc[1][j]);
            }
        }
        __syncthreads();
    }

#pragma unroll
    for (int i = 0; i < 2; i++)
#pragma unroll
        for (int j = 0; j < 4; j++)
            wmma::store_matrix_sync(&stage[(wm * 32 + i * 16) * LDS_ + wn * 64 + j * 16],
                                    acc[i][j], LDS_, wmma::mem_row_major);
    __syncthreads();
#pragma unroll
    for (int i = 0; i < 16; i++) {
        int lin = tid + i * 256;
        int r = lin >> 5, c4 = lin & 31;
        int col = c4 * 4;
        float4 v = *(float4*)(&stage[r * LDS_ + col]);
        size_t gi = (size_t)(row0 + r) * Nd + col0 + col;
        if (EPI == 1) {
            v.x = silu_f(v.x + bias[col0 + col + 0]);
            v.y = silu_f(v.y + bias[col0 + col + 1]);
            v.z = silu_f(v.z + bias[col0 + col + 2]);
            v.w = silu_f(v.w + bias[col0 + col + 3]);
            bf16 h[4], l[4];
            split_bf(v.x, h[0], l[0]); split_bf(v.y, h[1], l[1]);
            split_bf(v.z, h[2], l[2]); split_bf(v.w, h[3], l[3]);
            *(uint2*)(&Ch[gi]) = *(uint2*)h;
            *(uint2*)(&Cl[gi]) = *(uint2*)l;
            if (col0 < H_ * DV)
                *(float4*)(&C[gi]) = v;
        } else {
            float4 xo = *(const float4*)(&C[gi]);
            v.x = xo.x + v.x + bias[col0 + col + 0];
            v.y = xo.y + v.y + bias[col0 + col + 1];
            v.z = xo.z + v.z + bias[col0 + col + 2];
            v.w = xo.w + v.w + bias[col0 + col + 3];
            *(float4*)(&C[gi]) = v;
        }
    }
}

// ---------------- fused causal SiLU attention, 64x64 tiles, 512 thr, KV pipelined ----------------
#define QLD 136            // bf16 elems per row (128 + pad)
#define QTB 17408          // one 64x136 bf16 tile in bytes
#define SLD 68             // fp32 S
#define SBLD 72            // bf16 S hi/lo
#define OFF_QH 0
#define OFF_QL QTB
#define OFF_KV (2*QTB)     // 2 buffers x (KH,KL,VH,VL) each QTB
#define KVB    (4*QTB)     // one buffer set = 69632 B
#define OFF_S  (OFF_KV + 2*KVB)            // 174080
#define OFF_SH (OFF_S + 64*SLD*4)          // 191488
#define OFF_SL (OFF_SH + 64*SBLD*2)        // 200704
#define ASMEM  (OFF_SL + 64*SBLD*2)        // 209920 bytes

__global__ __launch_bounds__(512) void attn_kernel(const float* __restrict__ mask) {
    int qt = (gridDim.x - 1) - blockIdx.x;     // long tiles first
    int h = blockIdx.y, b = blockIdx.z;
    int q0 = qt * 64;
    int len = g_len[b];
    if (q0 >= len) return;
    int mtmax = qt;
    {
        int ml = (len - 1) >> 6;
        if (ml < mtmax) mtmax = ml;
    }

    extern __shared__ char smraw[];
    bf16* sQh = (bf16*)(smraw + OFF_QH);
    bf16* sQl = (bf16*)(smraw + OFF_QL);
    float* sS = (float*)(smraw + OFF_S);
    bf16* sSh = (bf16*)(smraw + OFF_SH);
    bf16* sSl = (bf16*)(smraw + OFF_SL);

    int tid = threadIdx.x;
    int warp = tid >> 5;
    int wr = warp >> 2, wc = warp & 3;          // 4x4 warp grid

    const size_t rs = UV;
    const size_t qoff = ((size_t)(b * N_) + q0) * rs + 2 * H_ * DV + h * DQK;
#pragma unroll
    for (int i = 0; i < 2; i++) {
        int lin = tid + i * 512;
        int r = lin >> 4, c8 = lin & 15;
        *(uint4*)(&sQh[r * QLD + c8 * 8]) = *(const uint4*)(g_uvh + qoff + (size_t)r * rs + c8 * 8);
        *(uint4*)(&sQl[r * QLD + c8 * 8]) = *(const uint4*)(g_uvl + qoff + (size_t)r * rs + c8 * 8);
    }

    // load K+V tile set for tile index mt into buffer buf (one commit group)
    auto load_kv = [&](int buf, int m0) {
        bf16* sKh = (bf16*)(smraw + OFF_KV + buf * KVB);
        bf16* sKl = sKh + QTB / 2;
        bf16* sVh = sKh + QTB;
        bf16* sVl = sKh + 3 * QTB / 2;
        const size_t koff = ((size_t)(b * N_) + m0) * rs + 2 * H_ * DV + H_ * DQK + h * DQK;
        const size_t voff = ((size_t)(b * N_) + m0) * rs + H_ * DV + h * DV;
#pragma unroll
        for (int i = 0; i < 2; i++) {
            int lin = tid + i * 512;
            int r = lin >> 4, c8 = lin & 15;
            cp16(&sKh[r * QLD + c8 * 8], g_uvh + koff + (size_t)r * rs + c8 * 8);
            cp16(&sKl[r * QLD + c8 * 8], g_uvl + koff + (size_t)r * rs + c8 * 8);
            cp16(&sVh[r * QLD + c8 * 8], g_uvh + voff + (size_t)r * rs + c8 * 8);
            cp16(&sVl[r * QLD + c8 * 8], g_uvl + voff + (size_t)r * rs + c8 * 8);
        }
        cp_commit();
    };

    wmma::fragment<wmma::accumulator, 16, 16, 16, float> accO[2];
#pragma unroll
    for (int j = 0; j < 2; j++) wmma::fill_fragment(accO[j], 0.f);

    load_kv(0, 0);

    for (int mt = 0; mt <= mtmax; mt++) {
        int buf = mt & 1;
        int m0 = mt * 64;
        if (mt < mtmax) { load_kv(buf ^ 1, (mt + 1) * 64); cp_wait<1>(); }
        else            { cp_wait<0>(); }
        __syncthreads();

        bf16* sKh = (bf16*)(smraw + OFF_KV + buf * KVB);
        bf16* sKl = sKh + QTB / 2;
        bf16* sVh = sKh + QTB;
        bf16* sVl = sKh + 3 * QTB / 2;

        // S = Q @ K^T : one 16x16 tile per warp
        wmma::fragment<wmma::accumulator, 16, 16, 16, float> accS;
        wmma::fill_fragment(accS, 0.f);
#pragma unroll
        for (int kk = 0; kk < DQK; kk += 16) {
            wmma::fragment<wmma::matrix_a, 16, 16, 16, bf16, wmma::row_major> ah, al;
            wmma::load_matrix_sync(ah, sQh + (wr * 16) * QLD + kk, QLD);
            wmma::load_matrix_sync(al, sQl + (wr * 16) * QLD + kk, QLD);
            wmma::fragment<wmma::matrix_b, 16, 16, 16, bf16, wmma::col_major> bh, bl;
            wmma::load_matrix_sync(bh, sKh + (wc * 16) * QLD + kk, QLD);
            wmma::load_matrix_sync(bl, sKl + (wc * 16) * QLD + kk, QLD);
            wmma::mma_sync(accS, ah, bl, accS);
            wmma::mma_sync(accS, al, bh, accS);
            wmma::mma_sync(accS, ah, bh, accS);
        }
        wmma::store_matrix_sync(&sS[(wr * 16) * SLD + wc * 16], accS,
                                SLD, wmma::mem_row_major);
        __syncthreads();

        // epilogue -> bf16 hi/lo S
#pragma unroll
        for (int i = 0; i < 8; i++) {
            int lin = tid + i * 512;
            int r = lin >> 6, c = lin & 63;
            int qrow = q0 + r, mcol = m0 + c;
            float v = sS[r * SLD + c] + g_rab[((size_t)b * N_ + qrow) * N_ + mcol];
            v = silu_f(v) * (1.0f / N_);
            if (mcol > qrow) v = 0.f;
            v *= mask[b * N_ + mcol];
            bf16 hh, ll; split_bf(v, hh, ll);
            sSh[r * SBLD + c] = hh;
            sSl[r * SBLD + c] = ll;
        }
        __syncthreads();

        // O += S @ V : warp computes 16x32
#pragma unroll
        for (int kk = 0; kk < 64; kk += 16) {
            wmma::fragment<wmma::matrix_a, 16, 16, 16, bf16, wmma::row_major> ah, al;
            wmma::load_matrix_sync(ah, sSh + (wr * 16) * SBLD + kk, SBLD);
            wmma::load_matrix_sync(al, sSl + (wr * 16) * SBLD + kk, SBLD);
#pragma unroll
            for (int j = 0; j < 2; j++) {
                wmma::fragment<wmma::matrix_b, 16, 16, 16, bf16, wmma::row_major> bh, bl;
                wmma::load_matrix_sync(bh, sVh + kk * QLD + wc * 32 + j * 16, QLD);
                wmma::load_matrix_sync(bl, sVl + kk * QLD + wc * 32 + j * 16, QLD);
                wmma::mma_sync(accO[j], ah, bl, accO[j]);
                wmma::mma_sync(accO[j], al, bh, accO[j]);
                wmma::mma_sync(accO[j], ah, bh, accO[j]);
            }
        }
        __syncthreads();
    }
#pragma unroll
    for (int j = 0; j < 2; j++)
        wmma::store_matrix_sync(&g_o[((size_t)(b * N_) + q0 + wr * 16) * D_ + h * DV + wc * 32 + j * 16],
                                accO[j], D_, wmma::mem_row_major);
}

// ---------------- pooling ----------------
__global__ void norm_rows_kernel(const float* __restrict__ in, float* __restrict__ out,
                                 int use_len) {
    int row = blockIdx.x;
    if (use_len && (row & (N_ - 1)) >= g_len[row >> 10]) return;   // dead row
    __shared__ float red[32];
    const float* x = in + (size_t)row * D_;
    int tid = threadIdx.x;
    float v[4]; float s2 = 0.f;
#pragma unroll
    for (int i = 0; i < 4; i++) { v[i] = x[tid + i * 256]; s2 += v[i] * v[i]; }
    float nrm = sqrtf(block_sum256(s2, red));
    float inv = 1.0f / fmaxf(nrm, 1e-12f);
#pragma unroll
    for (int i = 0; i < 4; i++) out[(size_t)row * D_ + tid + i * 256] = v[i] * inv;
}

__global__ void pool_part_kernel(const float* __restrict__ ue, const float* __restrict__ mask) {
    int b = blockIdx.y;
    int seg = blockIdx.z;
    int d = blockIdx.x * 256 + threadIdx.x;
    float acc = 0.f;
    int n0 = seg * 128;
#pragma unroll 4
    for (int n = n0; n < n0 + 128; n++)
        acc += ue[((size_t)b * N_ + n) * D_ + d] * mask[b * N_ + n];
    g_ppart[((size_t)seg * B_ + b) * D_ + d] = acc;
}

__global__ void pool_final_kernel(const float* __restrict__ ue) {
    int b = blockIdx.y;
    int d = blockIdx.x * 256 + threadIdx.x;
    float acc = 0.f;
#pragma unroll
    for (int seg = 0; seg < 8; seg++) acc += g_ppart[((size_t)seg * B_ + b) * D_ + d];
    int len = g_len[b];
    float last = ue[((size_t)b * N_ + (len - 1)) * D_ + d];
    g_pool[b * D_ + d] = 0.5f * (last + acc / (float)len);
}

// ---------------- host ----------------
extern "C" void kernel_launch(void* const* d_in, const int* in_sizes, int n_in,
                              void* d_out, int out_size) {
    const float* x      = (const float*)d_in[0];
    const int*   ts     = (const int*)d_in[1];
    const float* mask   = (const float*)d_in[2];
    const float* ln1_g  = (const float*)d_in[3];
    const float* ln1_b  = (const float*)d_in[4];
    const float* w_uvqk = (const float*)d_in[5];
    const float* b_uvqk = (const float*)d_in[6];
    const float* ln2_g  = (const float*)d_in[7];
    const float* ln2_b  = (const float*)d_in[8];
    const float* w_o    = (const float*)d_in[9];
    const float* b_o    = (const float*)d_in[10];
    const float* pos_w  = (const float*)d_in[11];
    const float* ts_w   = (const float*)d_in[12];
    float* out = (float*)d_out;

    static bool attr_done = false;
    if (!attr_done) {
        cudaFuncSetAttribute(gemm_bf16<1>, cudaFuncAttributeMaxDynamicSharedMemorySize, GSMEM);
        cudaFuncSetAttribute(gemm_bf16<2>, cudaFuncAttributeMaxDynamicSharedMemorySize, GSMEM);
        cudaFuncSetAttribute(attn_kernel,  cudaFuncAttributeMaxDynamicSharedMemorySize, ASMEM);
        attr_done = true;
    }

    float *px, *ph, *puv, *po, *ppool;
    bf16 *pah, *pal, *pwh, *pwl, *puvh, *puvl;
    cudaGetSymbolAddress((void**)&px, g_x);
    cudaGetSymbolAddress((void**)&ph, g_h);
    cudaGetSymbolAddress((void**)&puv, g_uvqk);
    cudaGetSymbolAddress((void**)&po, g_o);
    cudaGetSymbolAddress((void**)&ppool, g_pool);
    cudaGetSymbolAddress((void**)&pah, g_ah);
    cudaGetSymbolAddress((void**)&pal, g_al);
    cudaGetSymbolAddress((void**)&pwh, g_wh);
    cudaGetSymbolAddress((void**)&pwl, g_wl);
    cudaGetSymbolAddress((void**)&puvh, g_uvh);
    cudaGetSymbolAddress((void**)&puvl, g_uvl);

    prep_kernel<<<(B_*N_*D_)/256, 256>>>(x, mask);
    len_kernel<<<B_, 256>>>(mask);
    rab_kernel<<<(B_*N_*N_)/256, 256>>>(ts, pos_w, ts_w);

    for (int l = 0; l < 2; l++) {
        split_w_kernel<<<(D_*UV/4 + 255)/256, 256>>>(w_uvqk + (size_t)l*D_*UV, pwh, pwl, D_*UV/4);
        ln_kernel<<<B_*N_, 256>>>(px, ln1_g + l*D_, ln1_b + l*D_, pah, pal, nullptr);
        gemm_bf16<1><<<dim3(UV/BN, (B_*N_)/BM), 256, GSMEM>>>(
            pah, pal, pwh, pwl, puv, b_uvqk + l*UV, puvh, puvl, B_*N_, UV, D_);
        attn_kernel<<<dim3(N_/64, H_, B_), 512, ASMEM>>>(mask);
        ln_kernel<<<B_*N_, 256>>>(po, ln2_g + l*D_, ln2_b + l*D_, pah, pal, puv);
        split_w_kernel<<<(D_*D_/4 + 255)/256, 256>>>(w_o + (size_t)l*D_*D_, pwh, pwl, D_*D_/4);
        gemm_bf16<2><<<dim3(D_/BN, (B_*N_)/BM), 256, GSMEM>>>(
            pah, pal, pwh, pwl, px, b_o + l*D_, nullptr, nullptr, B_*N_, D_, D_);
    }

    norm_rows_kernel<<<B_*N_, 256>>>(px, ph, 1);
    pool_part_kernel<<<dim3(D_/256, B_, 8), 256>>>(ph, mask);
    pool_final_kernel<<<dim3(D_/256, B_), 256>>>(ph);
    norm_rows_kernel<<<B_, 256>>>(ppool, out, 0);
}

// round 17
// speedup vs baseline: 1.6024x; 1.0723x over previous
#include <cuda_runtime.h>
#include <cstdint>
#include <cuda_bf16.h>
#include <mma.h>
#include <math.h>

using namespace nvcuda;

#define B_  8
#define N_  1024
#define D_  1024
#define H_  8
#define DQK 128
#define DV  128
#define UV  4096
#define TB_ 128
#define LOG2C 0.69314718056f

typedef __nv_bfloat16 bf16;

// ---------------- scratch (zero-initialized device globals) ----------------
__device__ float g_x[B_*N_*D_];
__device__ float g_h[B_*N_*D_];
__device__ float g_uvqk[(size_t)B_*N_*UV];
__device__ float g_rab[(size_t)B_*N_*N_];
__device__ float g_o[B_*N_*D_];
__device__ float g_pool[B_*D_];
__device__ float g_ppart[8*B_*D_];
__device__ int   g_len[B_];
__device__ bf16  g_ah[B_*N_*D_];
__device__ bf16  g_al[B_*N_*D_];
__device__ bf16  g_wh[D_*UV];
__device__ bf16  g_wl[D_*UV];
__device__ bf16  g_uvh[(size_t)B_*N_*UV];
__device__ bf16  g_uvl[(size_t)B_*N_*UV];

// ---------------- helpers ----------------
__device__ __forceinline__ float block_sum256(float v, float* red) {
#pragma unroll
    for (int o = 16; o > 0; o >>= 1) v += __shfl_xor_sync(0xffffffffu, v, o);
    int warp = threadIdx.x >> 5, lane = threadIdx.x & 31;
    if (lane == 0) red[warp] = v;
    __syncthreads();
    if (warp == 0) {
        float t = (lane < 8) ? red[lane] : 0.f;
#pragma unroll
        for (int o = 4; o > 0; o >>= 1) t += __shfl_xor_sync(0xffffffffu, t, o);
        if (lane == 0) red[0] = t;
    }
    __syncthreads();
    float r = red[0];
    __syncthreads();
    return r;
}

// fast silu via HW intrinsics: rel err ~2^-21, below bf16-split noise floor
__device__ __forceinline__ float silu_f(float v) {
    return __fdividef(v, 1.f + __expf(-v));
}

__device__ __forceinline__ void split_bf(float v, bf16& h, bf16& l) {
    h = __float2bfloat16(v);
    l = __float2bfloat16(v - __bfloat162float(h));
}

__device__ __forceinline__ void cp16(void* dst, const void* src) {
    unsigned int s = (unsigned int)__cvta_generic_to_shared(dst);
    asm volatile("cp.async.cg.shared.global [%0], [%1], 16;\n" :: "r"(s), "l"(src));
}
__device__ __forceinline__ void cp_commit() { asm volatile("cp.async.commit_group;\n"); }
template <int NN>
__device__ __forceinline__ void cp_wait() { asm volatile("cp.async.wait_group %0;\n" :: "n"(NN)); }

// ---------------- elementwise ----------------
__global__ void prep_kernel(const float* __restrict__ x, const float* __restrict__ mask) {
    int idx = blockIdx.x * 256 + threadIdx.x;
    g_x[idx] = x[idx] * mask[idx >> 10];
}

__global__ void len_kernel(const float* __restrict__ mask) {
    __shared__ float red[32];
    int b = blockIdx.x;
    float s = 0.f;
    for (int i = threadIdx.x; i < N_; i += 256) s += mask[b * N_ + i];
    float t = block_sum256(s, red);
    if (threadIdx.x == 0) g_len[b] = (int)(t + 0.5f);
}

__global__ void rab_kernel(const int* __restrict__ ts,
                           const float* __restrict__ pos_w,
                           const float* __restrict__ ts_w) {
    int idx = blockIdx.x * 256 + threadIdx.x;
    int b = idx >> 20;
    int rem = idx & ((1 << 20) - 1);
    int n = rem >> 10;
    if (n >= g_len[b]) return;                 // dead q-row: rab never read live
    int m = rem & 1023;
    int tn = ts[b * N_ + ((n + 1 < N_) ? n + 1 : N_ - 1)];
    int dlt = tn - ts[b * N_ + m];
    float ad = fmaxf(fabsf((float)dlt), 1.0f);
    int bucket = (int)(__logf(ad) / LOG2C);
    bucket = bucket < 0 ? 0 : (bucket > TB_ ? TB_ : bucket);
    g_rab[idx] = pos_w[n - m + N_ - 1] + ts_w[bucket];
}

__global__ void split_w_kernel(const float* __restrict__ w, bf16* __restrict__ wh,
                               bf16* __restrict__ wl, int n4) {
    int i = blockIdx.x * 256 + threadIdx.x;
    if (i >= n4) return;
    float4 v = ((const float4*)w)[i];
    bf16 h[4], l[4];
    split_bf(v.x, h[0], l[0]); split_bf(v.y, h[1], l[1]);
    split_bf(v.z, h[2], l[2]); split_bf(v.w, h[3], l[3]);
    ((uint2*)wh)[i] = *(uint2*)h;
    ((uint2*)wl)[i] = *(uint2*)l;
}

// ---------------- layer norm -> bf16 hi/lo (skips dead rows) ----------------
__global__ void ln_kernel(const float* __restrict__ in,
                          const float* __restrict__ gamma,
                          const float* __restrict__ beta,
                          bf16* __restrict__ outh, bf16* __restrict__ outl,
                          const float* __restrict__ ubase) {
    int row = blockIdx.x;
    if ((row & (N_ - 1)) >= g_len[row >> 10]) return;   // dead row (never observed)
    __shared__ float red[32];
    const float* x = in + (size_t)row * D_;
    int tid = threadIdx.x;
    float v[4]; float s = 0.f;
#pragma unroll
    for (int i = 0; i < 4; i++) { v[i] = x[tid + i * 256]; s += v[i]; }
    float mu = block_sum256(s, red) * (1.0f / D_);
    float s2 = 0.f;
#pragma unroll
    for (int i = 0; i < 4; i++) { float d = v[i] - mu; s2 += d * d; }
    float var = block_sum256(s2, red) * (1.0f / D_);
    float inv = rsqrtf(var + 1e-6f);
#pragma unroll
    for (int i = 0; i < 4; i++) {
        int d = tid + i * 256;
        float y = (v[i] - mu) * inv * gamma[d] + beta[d];
        if (ubase) y *= ubase[(size_t)row * UV + d];
        bf16 h, l; split_bf(y, h, l);
        outh[(size_t)row * D_ + d] = h;
        outl[(size_t)row * D_ + d] = l;
    }
}

// ---------------- 3xBF16 GEMM, double-buffered cp.async, fused epilogue ----------------
#define BM 128
#define BN 128
#define BK 32
#define LDA_ 40
#define LDB_ 136
#define ABF (BM*LDA_)
#define BBF (BK*LDB_)
#define SBUF (2*ABF + 2*BBF)
#define GSMEM (2*SBUF*2)   // 75776 bytes -> 2 CTAs/SM
#define LDS_ 136

template <int EPI>
__global__ __launch_bounds__(256, 2) void gemm_bf16(const bf16* __restrict__ Ah,
                                                    const bf16* __restrict__ Al,
                                                    const bf16* __restrict__ Bh,
                                                    const bf16* __restrict__ Bl,
                                                    float* __restrict__ C,
                                                    const float* __restrict__ bias,
                                                    bf16* __restrict__ Ch,
                                                    bf16* __restrict__ Cl,
                                                    int M, int Nd, int K) {
    int row0 = blockIdx.y * BM;
    if ((row0 & (N_ - 1)) >= g_len[row0 >> 10]) return;

    extern __shared__ char smraw[];
    bf16* sm = (bf16*)smraw;
    float* stage = (float*)smraw;

    int tid = threadIdx.x;
    int warp = tid >> 5;
    int wm = warp >> 1, wn = warp & 1;
    int col0 = blockIdx.x * BN;

    wmma::fragment<wmma::accumulator, 16, 16, 16, float> acc[2][4];
#pragma unroll
    for (int i = 0; i < 2; i++)
#pragma unroll
        for (int j = 0; j < 4; j++) wmma::fill_fragment(acc[i][j], 0.f);

    auto load_tiles = [&](int buf, int k0) {
        bf16* sAh = sm + buf * SBUF;
        bf16* sAl = sAh + ABF;
        bf16* sBh = sAh + 2 * ABF;
        bf16* sBl = sBh + BBF;
#pragma unroll
        for (int i = 0; i < 2; i++) {
            int lin = tid + i * 256;
            int r = lin >> 2, c8 = lin & 3;
            cp16(&sAh[r * LDA_ + c8 * 8], Ah + (size_t)(row0 + r) * K + k0 + c8 * 8);
            cp16(&sAl[r * LDA_ + c8 * 8], Al + (size_t)(row0 + r) * K + k0 + c8 * 8);
        }
#pragma unroll
        for (int i = 0; i < 2; i++) {
            int lin = tid + i * 256;
            int r = lin >> 4, c8 = lin & 15;
            cp16(&sBh[r * LDB_ + c8 * 8], Bh + (size_t)(k0 + r) * Nd + col0 + c8 * 8);
            cp16(&sBl[r * LDB_ + c8 * 8], Bl + (size_t)(k0 + r) * Nd + col0 + c8 * 8);
        }
        cp_commit();
    };

    load_tiles(0, 0);

    int nk = K / BK;
    for (int it = 0; it < nk; it++) {
        int cur = it & 1;
        if (it + 1 < nk) { load_tiles(cur ^ 1, (it + 1) * BK); cp_wait<1>(); }
        else             { cp_wait<0>(); }
        __syncthreads();

        const bf16* sAh = sm + cur * SBUF;
        const bf16* sAl = sAh + ABF;
        const bf16* sBh = sAh + 2 * ABF;
        const bf16* sBl = sBh + BBF;
#pragma unroll
        for (int kk = 0; kk < BK; kk += 16) {
            wmma::fragment<wmma::matrix_a, 16, 16, 16, bf16, wmma::row_major> ah[2], al[2];
#pragma unroll
            for (int i = 0; i < 2; i++) {
                wmma::load_matrix_sync(ah[i], sAh + (wm * 32 + i * 16) * LDA_ + kk, LDA_);
                wmma::load_matrix_sync(al[i], sAl + (wm * 32 + i * 16) * LDA_ + kk, LDA_);
            }
#pragma unroll
            for (int j = 0; j < 4; j++) {
                wmma::fragment<wmma::matrix_b, 16, 16, 16, bf16, wmma::row_major> bh, bl;
                wmma::load_matrix_sync(bh, sBh + kk * LDB_ + wn * 64 + j * 16, LDB_);
                wmma::load_matrix_sync(bl, sBl + kk * LDB_ + wn * 64 + j * 16, LDB_);
                wmma::mma_sync(acc[0][j], ah[0], bl, acc[0][j]);
                wmma::mma_sync(acc[1][j], ah[1], bl, acc[1][j]);
                wmma::mma_sync(acc[0][j], al[0], bh, acc[0][j]);
                wmma::mma_sync(acc[1][j], al[1], bh, acc[1][j]);
                wmma::mma_sync(acc[0][j], ah[0], bh, acc[0][j]);
                wmma::mma_sync(acc[1][j], ah[1], bh, acc[1][j]);
            }
        }
        __syncthreads();
    }

#pragma unroll
    for (int i = 0; i < 2; i++)
#pragma unroll
        for (int j = 0; j < 4; j++)
            wmma::store_matrix_sync(&stage[(wm * 32 + i * 16) * LDS_ + wn * 64 + j * 16],
                                    acc[i][j], LDS_, wmma::mem_row_major);
    __syncthreads();
#pragma unroll
    for (int i = 0; i < 16; i++) {
        int lin = tid + i * 256;
        int r = lin >> 5, c4 = lin & 31;
        int col = c4 * 4;
        float4 v = *(float4*)(&stage[r * LDS_ + col]);
        size_t gi = (size_t)(row0 + r) * Nd + col0 + col;
        if (EPI == 1) {
            v.x = silu_f(v.x + bias[col0 + col + 0]);
            v.y = silu_f(v.y + bias[col0 + col + 1]);
            v.z = silu_f(v.z + bias[col0 + col + 2]);
            v.w = silu_f(v.w + bias[col0 + col + 3]);
            bf16 h[4], l[4];
            split_bf(v.x, h[0], l[0]); split_bf(v.y, h[1], l[1]);
            split_bf(v.z, h[2], l[2]); split_bf(v.w, h[3], l[3]);
            *(uint2*)(&Ch[gi]) = *(uint2*)h;
            *(uint2*)(&Cl[gi]) = *(uint2*)l;
            if (col0 < H_ * DV)
                *(float4*)(&C[gi]) = v;
        } else {
            float4 xo = *(const float4*)(&C[gi]);
            v.x = xo.x + v.x + bias[col0 + col + 0];
            v.y = xo.y + v.y + bias[col0 + col + 1];
            v.z = xo.z + v.z + bias[col0 + col + 2];
            v.w = xo.w + v.w + bias[col0 + col + 3];
            *(float4*)(&C[gi]) = v;
        }
    }
}

// ---------------- fused causal SiLU attention, 64x64 tiles, 512 thr, KV pipelined ----------------
#define QLD 136            // bf16 elems per row (128 + pad)
#define QTB 17408          // one 64x136 bf16 tile in bytes
#define SLD 68             // fp32 S
#define SBLD 72            // bf16 S hi/lo
#define OFF_QH 0
#define OFF_QL QTB
#define OFF_KV (2*QTB)     // 2 buffers x (KH,KL,VH,VL) each QTB
#define KVB    (4*QTB)     // one buffer set = 69632 B
#define OFF_S  (OFF_KV + 2*KVB)            // 174080
#define OFF_SH (OFF_S + 64*SLD*4)          // 191488
#define OFF_SL (OFF_SH + 64*SBLD*2)        // 200704
#define ASMEM  (OFF_SL + 64*SBLD*2)        // 209920 bytes

__global__ __launch_bounds__(512) void attn_kernel(const float* __restrict__ mask) {
    int qt = (gridDim.x - 1) - blockIdx.x;     // long tiles first
    int h = blockIdx.y, b = blockIdx.z;
    int q0 = qt * 64;
    int len = g_len[b];
    if (q0 >= len) return;
    int mtmax = qt;
    {
        int ml = (len - 1) >> 6;
        if (ml < mtmax) mtmax = ml;
    }

    extern __shared__ char smraw[];
    bf16* sQh = (bf16*)(smraw + OFF_QH);
    bf16* sQl = (bf16*)(smraw + OFF_QL);
    float* sS = (float*)(smraw + OFF_S);
    bf16* sSh = (bf16*)(smraw + OFF_SH);
    bf16* sSl = (bf16*)(smraw + OFF_SL);

    int tid = threadIdx.x;
    int warp = tid >> 5;
    int wr = warp >> 2, wc = warp & 3;          // 4x4 warp grid

    const size_t rs = UV;
    const size_t qoff = ((size_t)(b * N_) + q0) * rs + 2 * H_ * DV + h * DQK;
#pragma unroll
    for (int i = 0; i < 2; i++) {
        int lin = tid + i * 512;
        int r = lin >> 4, c8 = lin & 15;
        *(uint4*)(&sQh[r * QLD + c8 * 8]) = *(const uint4*)(g_uvh + qoff + (size_t)r * rs + c8 * 8);
        *(uint4*)(&sQl[r * QLD + c8 * 8]) = *(const uint4*)(g_uvl + qoff + (size_t)r * rs + c8 * 8);
    }

    // load K+V tile set for tile index mt into buffer buf (one commit group)
    auto load_kv = [&](int buf, int m0) {
        bf16* sKh = (bf16*)(smraw + OFF_KV + buf * KVB);
        bf16* sKl = sKh + QTB / 2;
        bf16* sVh = sKh + QTB;
        bf16* sVl = sKh + 3 * QTB / 2;
        const size_t koff = ((size_t)(b * N_) + m0) * rs + 2 * H_ * DV + H_ * DQK + h * DQK;
        const size_t voff = ((size_t)(b * N_) + m0) * rs + H_ * DV + h * DV;
#pragma unroll
        for (int i = 0; i < 2; i++) {
            int lin = tid + i * 512;
            int r = lin >> 4, c8 = lin & 15;
            cp16(&sKh[r * QLD + c8 * 8], g_uvh + koff + (size_t)r * rs + c8 * 8);
            cp16(&sKl[r * QLD + c8 * 8], g_uvl + koff + (size_t)r * rs + c8 * 8);
            cp16(&sVh[r * QLD + c8 * 8], g_uvh + voff + (size_t)r * rs + c8 * 8);
            cp16(&sVl[r * QLD + c8 * 8], g_uvl + voff + (size_t)r * rs + c8 * 8);
        }
        cp_commit();
    };

    wmma::fragment<wmma::accumulator, 16, 16, 16, float> accO[2];
#pragma unroll
    for (int j = 0; j < 2; j++) wmma::fill_fragment(accO[j], 0.f);

    load_kv(0, 0);

    for (int mt = 0; mt <= mtmax; mt++) {
        int buf = mt & 1;
        int m0 = mt * 64;
        if (mt < mtmax) { load_kv(buf ^ 1, (mt + 1) * 64); cp_wait<1>(); }
        else            { cp_wait<0>(); }
        __syncthreads();

        bf16* sKh = (bf16*)(smraw + OFF_KV + buf * KVB);
        bf16* sKl = sKh + QTB / 2;
        bf16* sVh = sKh + QTB;
        bf16* sVl = sKh + 3 * QTB / 2;

        // S = Q @ K^T : one 16x16 tile per warp
        wmma::fragment<wmma::accumulator, 16, 16, 16, float> accS;
        wmma::fill_fragment(accS, 0.f);
#pragma unroll
        for (int kk = 0; kk < DQK; kk += 16) {
            wmma::fragment<wmma::matrix_a, 16, 16, 16, bf16, wmma::row_major> ah, al;
            wmma::load_matrix_sync(ah, sQh + (wr * 16) * QLD + kk, QLD);
            wmma::load_matrix_sync(al, sQl + (wr * 16) * QLD + kk, QLD);
            wmma::fragment<wmma::matrix_b, 16, 16, 16, bf16, wmma::col_major> bh, bl;
            wmma::load_matrix_sync(bh, sKh + (wc * 16) * QLD + kk, QLD);
            wmma::load_matrix_sync(bl, sKl + (wc * 16) * QLD + kk, QLD);
            wmma::mma_sync(accS, ah, bl, accS);
            wmma::mma_sync(accS, al, bh, accS);
            wmma::mma_sync(accS, ah, bh, accS);
        }
        wmma::store_matrix_sync(&sS[(wr * 16) * SLD + wc * 16], accS,
                                SLD, wmma::mem_row_major);
        __syncthreads();

        // epilogue -> bf16 hi/lo S
#pragma unroll
        for (int i = 0; i < 8; i++) {
            int lin = tid + i * 512;
            int r = lin >> 6, c = lin & 63;
            int qrow = q0 + r, mcol = m0 + c;
            float v = sS[r * SLD + c] + g_rab[((size_t)b * N_ + qrow) * N_ + mcol];
            v = silu_f(v) * (1.0f / N_);
            if (mcol > qrow) v = 0.f;
            v *= mask[b * N_ + mcol];
            bf16 hh, ll; split_bf(v, hh, ll);
            sSh[r * SBLD + c] = hh;
            sSl[r * SBLD + c] = ll;
        }
        __syncthreads();

        // O += S @ V : warp computes 16x32
#pragma unroll
        for (int kk = 0; kk < 64; kk += 16) {
            wmma::fragment<wmma::matrix_a, 16, 16, 16, bf16, wmma::row_major> ah, al;
            wmma::load_matrix_sync(ah, sSh + (wr * 16) * SBLD + kk, SBLD);
            wmma::load_matrix_sync(al, sSl + (wr * 16) * SBLD + kk, SBLD);
#pragma unroll
            for (int j = 0; j < 2; j++) {
                wmma::fragment<wmma::matrix_b, 16, 16, 16, bf16, wmma::row_major> bh, bl;
                wmma::load_matrix_sync(bh, sVh + kk * QLD + wc * 32 + j * 16, QLD);
                wmma::load_matrix_sync(bl, sVl + kk * QLD + wc * 32 + j * 16, QLD);
                wmma::mma_sync(accO[j], ah, bl, accO[j]);
                wmma::mma_sync(accO[j], al, bh, accO[j]);
                wmma::mma_sync(accO[j], ah, bh, accO[j]);
            }
        }
        __syncthreads();
    }
#pragma unroll
    for (int j = 0; j < 2; j++)
        wmma::store_matrix_sync(&g_o[((size_t)(b * N_) + q0 + wr * 16) * D_ + h * DV + wc * 32 + j * 16],
                                accO[j], D_, wmma::mem_row_major);
}

// ---------------- pooling ----------------
__global__ void norm_rows_kernel(const float* __restrict__ in, float* __restrict__ out,
                                 int use_len) {
    int row = blockIdx.x;
    if (use_len && (row & (N_ - 1)) >= g_len[row >> 10]) return;   // dead row
    __shared__ float red[32];
    const float* x = in + (size_t)row * D_;
    int tid = threadIdx.x;
    float v[4]; float s2 = 0.f;
#pragma unroll
    for (int i = 0; i < 4; i++) { v[i] = x[tid + i * 256]; s2 += v[i] * v[i]; }
    float nrm = sqrtf(block_sum256(s2, red));
    float inv = 1.0f / fmaxf(nrm, 1e-12f);
#pragma unroll
    for (int i = 0; i < 4; i++) out[(size_t)row * D_ + tid + i * 256] = v[i] * inv;
}

__global__ void pool_part_kernel(const float* __restrict__ ue, const float* __restrict__ mask) {
    int b = blockIdx.y;
    int seg = blockIdx.z;
    int d = blockIdx.x * 256 + threadIdx.x;
    float acc = 0.f;
    int n0 = seg * 128;
#pragma unroll 4
    for (int n = n0; n < n0 + 128; n++)
        acc += ue[((size_t)b * N_ + n) * D_ + d] * mask[b * N_ + n];
    g_ppart[((size_t)seg * B_ + b) * D_ + d] = acc;
}

__global__ void pool_final_kernel(const float* __restrict__ ue) {
    int b = blockIdx.y;
    int d = blockIdx.x * 256 + threadIdx.x;
    float acc = 0.f;
#pragma unroll
    for (int seg = 0; seg < 8; seg++) acc += g_ppart[((size_t)seg * B_ + b) * D_ + d];
    int len = g_len[b];
    float last = ue[((size_t)b * N_ + (len - 1)) * D_ + d];
    g_pool[b * D_ + d] = 0.5f * (last + acc / (float)len);
}

// ---------------- host ----------------
extern "C" void kernel_launch(void* const* d_in, const int* in_sizes, int n_in,
                              void* d_out, int out_size) {
    const float* x      = (const float*)d_in[0];
    const int*   ts     = (const int*)d_in[1];
    const float* mask   = (const float*)d_in[2];
    const float* ln1_g  = (const float*)d_in[3];
    const float* ln1_b  = (const float*)d_in[4];
    const float* w_uvqk = (const float*)d_in[5];
    const float* b_uvqk = (const float*)d_in[6];
    const float* ln2_g  = (const float*)d_in[7];
    const float* ln2_b  = (const float*)d_in[8];
    const float* w_o    = (const float*)d_in[9];
    const float* b_o    = (const float*)d_in[10];
    const float* pos_w  = (const float*)d_in[11];
    const float* ts_w   = (const float*)d_in[12];
    float* out = (float*)d_out;

    static bool attr_done = false;
    if (!attr_done) {
        cudaFuncSetAttribute(gemm_bf16<1>, cudaFuncAttributeMaxDynamicSharedMemorySize, GSMEM);
        cudaFuncSetAttribute(gemm_bf16<2>, cudaFuncAttributeMaxDynamicSharedMemorySize, GSMEM);
        cudaFuncSetAttribute(attn_kernel,  cudaFuncAttributeMaxDynamicSharedMemorySize, ASMEM);
        attr_done = true;
    }

    float *px, *ph, *puv, *po, *ppool;
    bf16 *pah, *pal, *pwh, *pwl, *puvh, *puvl;
    cudaGetSymbolAddress((void**)&px, g_x);
    cudaGetSymbolAddress((void**)&ph, g_h);
    cudaGetSymbolAddress((void**)&puv, g_uvqk);
    cudaGetSymbolAddress((void**)&po, g_o);
    cudaGetSymbolAddress((void**)&ppool, g_pool);
    cudaGetSymbolAddress((void**)&pah, g_ah);
    cudaGetSymbolAddress((void**)&pal, g_al);
    cudaGetSymbolAddress((void**)&pwh, g_wh);
    cudaGetSymbolAddress((void**)&pwl, g_wl);
    cudaGetSymbolAddress((void**)&puvh, g_uvh);
    cudaGetSymbolAddress((void**)&puvl, g_uvl);

    prep_kernel<<<(B_*N_*D_)/256, 256>>>(x, mask);
    len_kernel<<<B_, 256>>>(mask);
    rab_kernel<<<(B_*N_*N_)/256, 256>>>(ts, pos_w, ts_w);

    for (int l = 0; l < 2; l++) {
        split_w_kernel<<<(D_*UV/4 + 255)/256, 256>>>(w_uvqk + (size_t)l*D_*UV, pwh, pwl, D_*UV/4);
        ln_kernel<<<B_*N_, 256>>>(px, ln1_g + l*D_, ln1_b + l*D_, pah, pal, nullptr);
        gemm_bf16<1><<<dim3(UV/BN, (B_*N_)/BM), 256, GSMEM>>>(
            pah, pal, pwh, pwl, puv, b_uvqk + l*UV, puvh, puvl, B_*N_, UV, D_);
        attn_kernel<<<dim3(N_/64, H_, B_), 512, ASMEM>>>(mask);
        ln_kernel<<<B_*N_, 256>>>(po, ln2_g + l*D_, ln2_b + l*D_, pah, pal, puv);
        split_w_kernel<<<(D_*D_/4 + 255)/256, 256>>>(w_o + (size_t)l*D_*D_, pwh, pwl, D_*D_/4);
        gemm_bf16<2><<<dim3(D_/BN, (B_*N_)/BM), 256, GSMEM>>>(
            pah, pal, pwh, pwl, px, b_o + l*D_, nullptr, nullptr, B_*N_, D_, D_);
    }

    norm_rows_kernel<<<B_*N_, 256>>>(px, ph, 1);
    pool_part_kernel<<<dim3(D_/256, B_, 8), 256>>>(ph, mask);
    pool_final_kernel<<<dim3(D_/256, B_), 256>>>(ph);
    norm_rows_kernel<<<B_, 256>>>(ppool, out, 0);
}